// round 5
// baseline (speedup 1.0000x reference)
#include <cuda_runtime.h>
#include <math.h>

#define B_  2
#define T_  2048
#define C_  1024
#define H_  16
#define HD_ 64
#define N1_ 6
#define N2_ 4

// ---------------- scratch (device globals; no allocs allowed) ----------------
__device__ float g_qkv[B_ * T_ * 3 * C_];          // [B,T,3C]
__device__ float g_q[B_ * H_ * T_ * HD_];          // [B,H,T,64]  (scales folded in)
__device__ float g_k[B_ * H_ * T_ * HD_];
__device__ float g_v[B_ * H_ * T_ * HD_];
__device__ float g_y[B_ * T_ * C_];                // attention out, [B,T,C]
__device__ float g_tq[B_ * N2_ * T_];              // hyperbolic tq
__device__ float g_tk[B_ * N2_ * T_];              // hyperbolic tk

// ---------------- GEMM: C[m,n] = sum_k A[m,k]*B[n,k] (+bias[n]) --------------
// A: [M,K] row-major, B: [N,K] row-major, C: [M,N] row-major.
// 64x64x16 tiles, 256 threads, 4x4 per-thread micro-tile.
template <bool BIAS>
__global__ void __launch_bounds__(256) gemm_nt(const float* __restrict__ A,
                                               const float* __restrict__ Bm,
                                               const float* __restrict__ bias,
                                               float* __restrict__ Cc,
                                               int M, int N, int K)
{
    __shared__ float As[16][68];
    __shared__ float Bs[16][68];

    const int tid = threadIdx.x;
    const int m0 = blockIdx.y * 64;
    const int n0 = blockIdx.x * 64;

    const int lrow = tid >> 2;        // 0..63
    const int lc4  = tid & 3;         // 0..3 (float4 column within BK=16)

    const int tx = tid & 15;
    const int ty = tid >> 4;

    float c[4][4];
#pragma unroll
    for (int i = 0; i < 4; ++i)
#pragma unroll
        for (int j = 0; j < 4; ++j) c[i][j] = 0.f;

    for (int k0 = 0; k0 < K; k0 += 16) {
        // load A tile (transposed store: As[k][m])
        {
            float4 av = *(const float4*)(A + (long)(m0 + lrow) * K + k0 + lc4 * 4);
            As[lc4 * 4 + 0][lrow] = av.x;
            As[lc4 * 4 + 1][lrow] = av.y;
            As[lc4 * 4 + 2][lrow] = av.z;
            As[lc4 * 4 + 3][lrow] = av.w;
            float4 bv = *(const float4*)(Bm + (long)(n0 + lrow) * K + k0 + lc4 * 4);
            Bs[lc4 * 4 + 0][lrow] = bv.x;
            Bs[lc4 * 4 + 1][lrow] = bv.y;
            Bs[lc4 * 4 + 2][lrow] = bv.z;
            Bs[lc4 * 4 + 3][lrow] = bv.w;
        }
        __syncthreads();

#pragma unroll
        for (int kk = 0; kk < 16; ++kk) {
            float4 a4 = *(const float4*)&As[kk][ty * 4];
            float4 b4 = *(const float4*)&Bs[kk][tx * 4];
            c[0][0] = fmaf(a4.x, b4.x, c[0][0]);
            c[0][1] = fmaf(a4.x, b4.y, c[0][1]);
            c[0][2] = fmaf(a4.x, b4.z, c[0][2]);
            c[0][3] = fmaf(a4.x, b4.w, c[0][3]);
            c[1][0] = fmaf(a4.y, b4.x, c[1][0]);
            c[1][1] = fmaf(a4.y, b4.y, c[1][1]);
            c[1][2] = fmaf(a4.y, b4.z, c[1][2]);
            c[1][3] = fmaf(a4.y, b4.w, c[1][3]);
            c[2][0] = fmaf(a4.z, b4.x, c[2][0]);
            c[2][1] = fmaf(a4.z, b4.y, c[2][1]);
            c[2][2] = fmaf(a4.z, b4.z, c[2][2]);
            c[2][3] = fmaf(a4.z, b4.w, c[2][3]);
            c[3][0] = fmaf(a4.w, b4.x, c[3][0]);
            c[3][1] = fmaf(a4.w, b4.y, c[3][1]);
            c[3][2] = fmaf(a4.w, b4.z, c[3][2]);
            c[3][3] = fmaf(a4.w, b4.w, c[3][3]);
        }
        __syncthreads();
    }

#pragma unroll
    for (int i = 0; i < 4; ++i) {
        const int m = m0 + ty * 4 + i;
        const int n = n0 + tx * 4;
        float4 r;
        r.x = c[i][0]; r.y = c[i][1]; r.z = c[i][2]; r.w = c[i][3];
        if (BIAS) {
            float4 bb = *(const float4*)(bias + n);
            r.x += bb.x; r.y += bb.y; r.z += bb.z; r.w += bb.w;
        }
        *(float4*)(Cc + (long)m * N + n) = r;
    }
}

// ---------------- RoPE + per-head prep ---------------------------------------
// One block per (b,t). 512 threads: warp w == head h (32 rotary pairs/head).
__global__ void __launch_bounds__(512) rope_kernel(const float* __restrict__ curvp)
{
    const int bt = blockIdx.x;
    const int b = bt / T_;
    const int t = bt % T_;
    const int tid = threadIdx.x;
    const int h = tid >> 5;
    const int j = tid & 31;

    __shared__ float s_inv[32];
    if (tid < 32) s_inv[tid] = (float)pow(10000.0, -(double)tid / 32.0);
    __syncthreads();

    const float* qp = g_qkv + (long)bt * (3 * C_);

    float q1 = qp[h * 64 + j];
    float q2 = qp[h * 64 + 32 + j];
    float k1 = qp[C_ + h * 64 + j];
    float k2 = qp[C_ + h * 64 + 32 + j];

    float fr = (float)t * s_inv[j];
    float cs, sn;
    sincosf(fr, &sn, &cs);

    float q1r = q1 * cs + q2 * sn;
    float q2r = -q1 * sn + q2 * cs;
    float k1r = k1 * cs + k2 * sn;
    float k2r = -k1 * sn + k2 * cs;

    // head-wide sum of squares (rotation preserves norm)
    float sq = q1 * q1 + q2 * q2;
    float sk = k1 * k1 + k2 * k2;
#pragma unroll
    for (int o = 16; o > 0; o >>= 1) {
        sq += __shfl_xor_sync(0xffffffffu, sq, o);
        sk += __shfl_xor_sync(0xffffffffu, sk, o);
    }

    float qscale = 1.f, kscale = 1.f;
    if (h < N1_) {
        qscale = 0.125f;                       // 1/sqrt(HD)
    } else if (h < N1_ + N2_) {
        float curv = curvp[h - N1_];
        if (j == 0) {
            g_tq[(b * N2_ + (h - N1_)) * T_ + t] = sqrtf(1.0f / curv + sq);
            g_tk[(b * N2_ + (h - N1_)) * T_ + t] = sqrtf(1.0f / curv + sk);
        }
    } else {
        qscale = 8.0f / fmaxf(sqrtf(sq), 1e-12f);  // sqrt(HD) * qn
        kscale = 1.0f / fmaxf(sqrtf(sk), 1e-12f);
    }

    const long o = ((long)(b * H_ + h) * T_ + t) * HD_;
    g_q[o + j]      = q1r * qscale;
    g_q[o + 32 + j] = q2r * qscale;
    g_k[o + j]      = k1r * kscale;
    g_k[o + 32 + j] = k2r * kscale;

    // v copy: 2 contiguous elements per thread within this head
    float2 vv = *(const float2*)(qp + 2 * C_ + 2 * tid);
    *(float2*)(g_v + o + (j * 2)) = vv;
}

// ---------------- attention (flash-style, fp32) -------------------------------
// grid (T/64, H, B), 128 threads. 2 threads per query row (32 dims each).
__global__ void __launch_bounds__(128) attn_kernel(const float* __restrict__ curvp)
{
    __shared__ float Ks[64][68];
    __shared__ float Vs[64][68];
    __shared__ float tks[64];

    const int i0 = blockIdx.x * 64;
    const int h  = blockIdx.y;
    const int b  = blockIdx.z;
    const int tid = threadIdx.x;
    const int row = tid >> 1;
    const int half = tid & 1;
    const int d0 = half * 32;
    const int i = i0 + row;

    const int variant = (h < N1_) ? 0 : ((h < N1_ + N2_) ? 1 : 2);

    const long base = (long)(b * H_ + h) * T_ * HD_;

    float4 qv[8];
#pragma unroll
    for (int j4 = 0; j4 < 8; ++j4)
        qv[j4] = *(const float4*)(g_q + base + (long)i * HD_ + d0 + 4 * j4);

    float curv = 0.f, invsqc = 0.f, tqi = 0.f;
    if (variant == 1) {
        curv = curvp[h - N1_];
        invsqc = sqrtf(1.0f / curv);
        tqi = g_tq[(b * N2_ + (h - N1_)) * T_ + i];
    }

    float m_run = -1e30f, l_run = 0.f;
    float acc[32];
#pragma unroll
    for (int j = 0; j < 32; ++j) acc[j] = 0.f;

    for (int s0 = 0; s0 <= i0; s0 += 64) {
#pragma unroll
        for (int j4 = 0; j4 < 8; ++j4) {
            *(float4*)&Ks[row][d0 + 4 * j4] =
                *(const float4*)(g_k + base + (long)(s0 + row) * HD_ + d0 + 4 * j4);
            *(float4*)&Vs[row][d0 + 4 * j4] =
                *(const float4*)(g_v + base + (long)(s0 + row) * HD_ + d0 + 4 * j4);
        }
        if (variant == 1 && tid < 64)
            tks[tid] = g_tk[(b * N2_ + (h - N1_)) * T_ + s0 + tid];
        __syncthreads();

        float scr[64];
        const int smax = i - s0;
        float tmax = -1e30f;
#pragma unroll
        for (int s = 0; s < 64; ++s) {
            float p = 0.f;
#pragma unroll
            for (int j4 = 0; j4 < 8; ++j4) {
                float4 kk = *(const float4*)&Ks[s][d0 + 4 * j4];
                p = fmaf(qv[j4].x, kk.x, p);
                p = fmaf(qv[j4].y, kk.y, p);
                p = fmaf(qv[j4].z, kk.z, p);
                p = fmaf(qv[j4].w, kk.w, p);
            }
            p += __shfl_xor_sync(0xffffffffu, p, 1);
            float sc;
            if (variant == 1) {
                float a = fmaxf(curv * (tqi * tks[s] - p), 1.0f + 1e-7f);
                sc = 1.0f / (1e-6f + invsqc * acoshf(a));
            } else {
                sc = p;
            }
            sc = (s <= smax) ? sc : -1e30f;
            scr[s] = sc;
            tmax = fmaxf(tmax, sc);
        }

        float mnew = fmaxf(m_run, tmax);
        float rescale = __expf(m_run - mnew);
        l_run *= rescale;
#pragma unroll
        for (int j = 0; j < 32; ++j) acc[j] *= rescale;

#pragma unroll
        for (int s = 0; s < 64; ++s) {
            float ps = __expf(scr[s] - mnew);
            l_run += ps;
#pragma unroll
            for (int j4 = 0; j4 < 8; ++j4) {
                float4 vv = *(const float4*)&Vs[s][d0 + 4 * j4];
                acc[j4 * 4 + 0] = fmaf(ps, vv.x, acc[j4 * 4 + 0]);
                acc[j4 * 4 + 1] = fmaf(ps, vv.y, acc[j4 * 4 + 1]);
                acc[j4 * 4 + 2] = fmaf(ps, vv.z, acc[j4 * 4 + 2]);
                acc[j4 * 4 + 3] = fmaf(ps, vv.w, acc[j4 * 4 + 3]);
            }
        }
        m_run = mnew;
        __syncthreads();
    }

    const float inv_l = 1.0f / l_run;
    float* yo = g_y + (long)(b * T_ + i) * C_ + h * HD_ + d0;
#pragma unroll
    for (int j4 = 0; j4 < 8; ++j4) {
        float4 r;
        r.x = acc[j4 * 4 + 0] * inv_l;
        r.y = acc[j4 * 4 + 1] * inv_l;
        r.z = acc[j4 * 4 + 2] * inv_l;
        r.w = acc[j4 * 4 + 3] * inv_l;
        *(float4*)(yo + 4 * j4) = r;
    }
}

// ---------------- launch ------------------------------------------------------
extern "C" void kernel_launch(void* const* d_in, const int* in_sizes, int n_in,
                              void* d_out, int out_size)
{
    const float* x       = (const float*)d_in[0];
    const float* qkv_w   = (const float*)d_in[1];
    const float* proj_w  = (const float*)d_in[2];
    const float* proj_b  = (const float*)d_in[3];
    const float* curv    = (const float*)d_in[4];
    float* out = (float*)d_out;

    float *qkv, *y;
    cudaGetSymbolAddress((void**)&qkv, g_qkv);
    cudaGetSymbolAddress((void**)&y,   g_y);

    // 1) qkv = x @ qkv_w.T           [4096,3072]
    gemm_nt<false><<<dim3((3 * C_) / 64, (B_ * T_) / 64), 256>>>(
        x, qkv_w, nullptr, qkv, B_ * T_, 3 * C_, C_);

    // 2) rope + head layout + scale folding + hyperbolic tq/tk
    rope_kernel<<<B_ * T_, 512>>>(curv);

    // 3) multi-geometry causal attention -> g_y [B,T,C]
    attn_kernel<<<dim3(T_ / 64, H_, B_), 128>>>(curv);

    // 4) out = y @ proj_w.T + proj_b
    gemm_nt<true><<<dim3(C_ / 64, (B_ * T_) / 64), 256>>>(
        y, proj_w, proj_b, out, B_ * T_, C_, C_);
}

// round 7
// speedup vs baseline: 4.2048x; 4.2048x over previous
#include <cuda_runtime.h>
#include <math.h>

#define B_  2
#define T_  2048
#define C_  1024
#define H_  16
#define HD_ 64
#define N1_ 6
#define N2_ 4

// ---------------- scratch (device globals; no allocs allowed) ----------------
__device__ float g_qkv[B_ * T_ * 3 * C_];          // [B,T,3C]
__device__ float g_q[B_ * H_ * T_ * HD_];          // [B,H,T,64]  (scales folded in)
__device__ float g_k[B_ * H_ * T_ * HD_];
__device__ float g_v[B_ * H_ * T_ * HD_];
__device__ float g_y[B_ * T_ * C_];                // attention out, [B,T,C]
__device__ float g_tq[B_ * N2_ * T_];              // hyperbolic tq
__device__ float g_tk[B_ * N2_ * T_];              // hyperbolic tk

// ---------------- tf32 mma helpers -------------------------------------------
__device__ __forceinline__ unsigned f2tf32(float x) {
    unsigned u;
    asm("cvt.rna.tf32.f32 %0, %1;" : "=r"(u) : "f"(x));
    return u;
}

// D = A(16x8, row) * B(8x8, col) + D, fp32 accum
__device__ __forceinline__ void mma_tf32(float* c, const unsigned* a,
                                         unsigned b0, unsigned b1) {
    asm volatile(
        "mma.sync.aligned.m16n8k8.row.col.f32.tf32.tf32.f32 "
        "{%0,%1,%2,%3}, {%4,%5,%6,%7}, {%8,%9}, {%0,%1,%2,%3};"
        : "+f"(c[0]), "+f"(c[1]), "+f"(c[2]), "+f"(c[3])
        : "r"(a[0]), "r"(a[1]), "r"(a[2]), "r"(a[3]), "r"(b0), "r"(b1));
}

// ---------------- GEMM: C[m,n] = sum_k A[m,k]*B[n,k] (+bias[n]) --------------
// CTA: 256 thr (8 warps), tile 128(M) x 64(N), k-chunk 16. Warp = 32x32.
template <bool BIAS>
__global__ void __launch_bounds__(256) gemm_tf32(const float* __restrict__ A,
                                                 const float* __restrict__ Bm,
                                                 const float* __restrict__ bias,
                                                 float* __restrict__ Cc,
                                                 int M, int N, int K)
{
    __shared__ unsigned As[128 * 20];   // tf32 bits, row stride 20 (conflict-free frags)
    __shared__ unsigned Bs[64 * 20];

    const int tid = threadIdx.x;
    const int lane = tid & 31;
    const int wid = tid >> 5;
    const int g = lane >> 2;      // 0..7
    const int c4 = lane & 3;      // 0..3
    const int m0 = blockIdx.y * 128;
    const int n0 = blockIdx.x * 64;
    const int wm = (wid >> 1) * 32;
    const int wn = (wid & 1) * 32;

    float acc[2][4][4];
#pragma unroll
    for (int mt = 0; mt < 2; ++mt)
#pragma unroll
        for (int nt = 0; nt < 4; ++nt)
#pragma unroll
            for (int r = 0; r < 4; ++r) acc[mt][nt][r] = 0.f;

    for (int k0 = 0; k0 < K; k0 += 16) {
        // A tile 128x16 (2 float4 per thread)
#pragma unroll
        for (int it = 0; it < 2; ++it) {
            int idx = tid + it * 256;
            int row = idx >> 2, j = (idx & 3) * 4;
            float4 v = *(const float4*)(A + (long)(m0 + row) * K + k0 + j);
            uint4 u;
            u.x = f2tf32(v.x); u.y = f2tf32(v.y); u.z = f2tf32(v.z); u.w = f2tf32(v.w);
            *(uint4*)&As[row * 20 + j] = u;
        }
        // B tile 64x16 (1 float4 per thread)
        {
            int row = tid >> 2, j = (tid & 3) * 4;
            float4 v = *(const float4*)(Bm + (long)(n0 + row) * K + k0 + j);
            uint4 u;
            u.x = f2tf32(v.x); u.y = f2tf32(v.y); u.z = f2tf32(v.z); u.w = f2tf32(v.w);
            *(uint4*)&Bs[row * 20 + j] = u;
        }
        __syncthreads();

#pragma unroll
        for (int ks = 0; ks < 2; ++ks) {
            const int kc = 8 * ks + c4;
            unsigned af[2][4], bf[4][2];
#pragma unroll
            for (int mt = 0; mt < 2; ++mt) {
                int r = wm + 16 * mt + g;
                af[mt][0] = As[r * 20 + kc];
                af[mt][1] = As[(r + 8) * 20 + kc];
                af[mt][2] = As[r * 20 + kc + 4];
                af[mt][3] = As[(r + 8) * 20 + kc + 4];
            }
#pragma unroll
            for (int nt = 0; nt < 4; ++nt) {
                int n = wn + 8 * nt + g;
                bf[nt][0] = Bs[n * 20 + kc];
                bf[nt][1] = Bs[n * 20 + kc + 4];
            }
#pragma unroll
            for (int mt = 0; mt < 2; ++mt)
#pragma unroll
                for (int nt = 0; nt < 4; ++nt)
                    mma_tf32(acc[mt][nt], af[mt], bf[nt][0], bf[nt][1]);
        }
        __syncthreads();
    }

#pragma unroll
    for (int mt = 0; mt < 2; ++mt) {
#pragma unroll
        for (int nt = 0; nt < 4; ++nt) {
            const int rr = m0 + wm + 16 * mt + g;
            const int cc = n0 + wn + 8 * nt + 2 * c4;
            float b0v = 0.f, b1v = 0.f;
            if (BIAS) { b0v = bias[cc]; b1v = bias[cc + 1]; }
            float2 v0; v0.x = acc[mt][nt][0] + b0v; v0.y = acc[mt][nt][1] + b1v;
            float2 v1; v1.x = acc[mt][nt][2] + b0v; v1.y = acc[mt][nt][3] + b1v;
            *(float2*)(Cc + (long)rr * N + cc) = v0;
            *(float2*)(Cc + (long)(rr + 8) * N + cc) = v1;
        }
    }
}

// ---------------- RoPE + per-head prep ---------------------------------------
__global__ void __launch_bounds__(512) rope_kernel(const float* __restrict__ curvp)
{
    const int bt = blockIdx.x;
    const int b = bt / T_;
    const int t = bt % T_;
    const int tid = threadIdx.x;
    const int h = tid >> 5;
    const int j = tid & 31;

    __shared__ float s_inv[32];
    if (tid < 32) s_inv[tid] = (float)pow(10000.0, -(double)tid / 32.0);
    __syncthreads();

    const float* qp = g_qkv + (long)bt * (3 * C_);

    float q1 = qp[h * 64 + j];
    float q2 = qp[h * 64 + 32 + j];
    float k1 = qp[C_ + h * 64 + j];
    float k2 = qp[C_ + h * 64 + 32 + j];

    float fr = (float)t * s_inv[j];
    float cs, sn;
    sincosf(fr, &sn, &cs);

    float q1r = q1 * cs + q2 * sn;
    float q2r = -q1 * sn + q2 * cs;
    float k1r = k1 * cs + k2 * sn;
    float k2r = -k1 * sn + k2 * cs;

    float sq = q1 * q1 + q2 * q2;
    float sk = k1 * k1 + k2 * k2;
#pragma unroll
    for (int o = 16; o > 0; o >>= 1) {
        sq += __shfl_xor_sync(0xffffffffu, sq, o);
        sk += __shfl_xor_sync(0xffffffffu, sk, o);
    }

    float qscale = 1.f, kscale = 1.f;
    if (h < N1_) {
        qscale = 0.125f;
    } else if (h < N1_ + N2_) {
        float curv = curvp[h - N1_];
        if (j == 0) {
            g_tq[(b * N2_ + (h - N1_)) * T_ + t] = sqrtf(1.0f / curv + sq);
            g_tk[(b * N2_ + (h - N1_)) * T_ + t] = sqrtf(1.0f / curv + sk);
        }
    } else {
        qscale = 8.0f / fmaxf(sqrtf(sq), 1e-12f);
        kscale = 1.0f / fmaxf(sqrtf(sk), 1e-12f);
    }

    const long o = ((long)(b * H_ + h) * T_ + t) * HD_;
    g_q[o + j]      = q1r * qscale;
    g_q[o + 32 + j] = q2r * qscale;
    g_k[o + j]      = k1r * kscale;
    g_k[o + 32 + j] = k2r * kscale;

    float2 vv = *(const float2*)(qp + 2 * C_ + 2 * tid);
    *(float2*)(g_v + o + (j * 2)) = vv;
}

// ---------------- attention: FA2-style with tf32 mma --------------------------
// grid (T/64, H, B), 128 threads (4 warps). Warp w: q rows i0+16w .. +15 (m16).
__device__ __forceinline__ float hypscore(float p, float tq, float tk,
                                          float curv, float invsqc) {
    float a = fmaxf(curv * (tq * tk - p), 1.0f + 1e-7f);
    return 1.0f / (1e-6f + invsqc * acoshf(a));
}

__global__ void __launch_bounds__(128) attn_mma(const float* __restrict__ curvp)
{
    __shared__ unsigned Ks[64 * 68];   // tf32 bits; stride 68 (≡4 mod 32)
    __shared__ unsigned Vs[64 * 72];   // tf32 bits; stride 72 (≡8 mod 32)
    __shared__ float tks[64];

    const int i0 = blockIdx.x * 64;
    const int h  = blockIdx.y;
    const int b  = blockIdx.z;
    const int tid = threadIdx.x;
    const int w = tid >> 5;
    const int lane = tid & 31;
    const int g = lane >> 2;
    const int c4 = lane & 3;
    const int variant = (h < N1_) ? 0 : ((h < N1_ + N2_) ? 1 : 2);
    const long base = (long)(b * H_ + h) * T_ * HD_;
    const int r0 = 16 * w + g;         // warp-local row (and r0+8)

    // ---- stage Q tile into Ks (raw fp32 bits), build register A-fragments ----
    for (int idx = tid; idx < 64 * 16; idx += 128) {
        int row = idx >> 4, j = (idx & 15) * 4;
        float4 v = *(const float4*)(g_q + base + (long)(i0 + row) * HD_ + j);
        uint4 u;
        u.x = __float_as_uint(v.x); u.y = __float_as_uint(v.y);
        u.z = __float_as_uint(v.z); u.w = __float_as_uint(v.w);
        *(uint4*)&Ks[row * 68 + j] = u;
    }
    __syncthreads();

    unsigned qa[8][4];
#pragma unroll
    for (int kt = 0; kt < 8; ++kt) {
        int col = 8 * kt + c4;
        qa[kt][0] = f2tf32(__uint_as_float(Ks[r0 * 68 + col]));
        qa[kt][1] = f2tf32(__uint_as_float(Ks[(r0 + 8) * 68 + col]));
        qa[kt][2] = f2tf32(__uint_as_float(Ks[r0 * 68 + col + 4]));
        qa[kt][3] = f2tf32(__uint_as_float(Ks[(r0 + 8) * 68 + col + 4]));
    }

    float curv = 0.f, invsqc = 0.f, tq0 = 0.f, tq1 = 0.f;
    if (variant == 1) {
        curv = curvp[h - N1_];
        invsqc = sqrtf(1.0f / curv);
        tq0 = g_tq[(b * N2_ + (h - N1_)) * T_ + i0 + r0];
        tq1 = g_tq[(b * N2_ + (h - N1_)) * T_ + i0 + r0 + 8];
    }
    __syncthreads();

    float m0r = -1e30f, m1r = -1e30f, l0 = 0.f, l1 = 0.f;
    float acc[8][4];
#pragma unroll
    for (int nt = 0; nt < 8; ++nt)
#pragma unroll
        for (int r = 0; r < 4; ++r) acc[nt][r] = 0.f;

    const int srcA = (lane & 28) | (c4 >> 1);
    const int srcB = srcA + 2;
    const bool odd = (c4 & 1);

    for (int s0 = 0; s0 <= i0; s0 += 64) {
        // load K/V tiles, converting to tf32 at store time
        for (int idx = tid; idx < 64 * 16; idx += 128) {
            int row = idx >> 4, j = (idx & 15) * 4;
            float4 kv = *(const float4*)(g_k + base + (long)(s0 + row) * HD_ + j);
            uint4 uk;
            uk.x = f2tf32(kv.x); uk.y = f2tf32(kv.y);
            uk.z = f2tf32(kv.z); uk.w = f2tf32(kv.w);
            *(uint4*)&Ks[row * 68 + j] = uk;
            float4 vv = *(const float4*)(g_v + base + (long)(s0 + row) * HD_ + j);
            uint4 uv;
            uv.x = f2tf32(vv.x); uv.y = f2tf32(vv.y);
            uv.z = f2tf32(vv.z); uv.w = f2tf32(vv.w);
            *(uint4*)&Vs[row * 72 + j] = uv;
        }
        if (variant == 1 && tid < 64)
            tks[tid] = g_tk[(b * N2_ + (h - N1_)) * T_ + s0 + tid];
        __syncthreads();

        // ---- QK^T: scores 16x64 per warp ----
        float sc[8][4];
#pragma unroll
        for (int nt = 0; nt < 8; ++nt)
#pragma unroll
            for (int r = 0; r < 4; ++r) sc[nt][r] = 0.f;

#pragma unroll
        for (int nt = 0; nt < 8; ++nt) {
#pragma unroll
            for (int kt = 0; kt < 8; ++kt) {
                unsigned b0 = Ks[(8 * nt + g) * 68 + 8 * kt + c4];
                unsigned b1 = Ks[(8 * nt + g) * 68 + 8 * kt + c4 + 4];
                mma_tf32(sc[nt], qa[kt], b0, b1);
            }
        }

        // ---- transform + mask + row max ----
        float mloc0 = -1e30f, mloc1 = -1e30f;
#pragma unroll
        for (int nt = 0; nt < 8; ++nt) {
            const int cb = 8 * nt + 2 * c4;
            if (variant == 1) {
                float tk0 = tks[cb], tk1 = tks[cb + 1];
                sc[nt][0] = hypscore(sc[nt][0], tq0, tk0, curv, invsqc);
                sc[nt][1] = hypscore(sc[nt][1], tq0, tk1, curv, invsqc);
                sc[nt][2] = hypscore(sc[nt][2], tq1, tk0, curv, invsqc);
                sc[nt][3] = hypscore(sc[nt][3], tq1, tk1, curv, invsqc);
            }
            if (s0 == i0) {   // only the diagonal tile needs causal masking
                if (cb > r0)         sc[nt][0] = -1e30f;
                if (cb + 1 > r0)     sc[nt][1] = -1e30f;
                if (cb > r0 + 8)     sc[nt][2] = -1e30f;
                if (cb + 1 > r0 + 8) sc[nt][3] = -1e30f;
            }
            mloc0 = fmaxf(mloc0, fmaxf(sc[nt][0], sc[nt][1]));
            mloc1 = fmaxf(mloc1, fmaxf(sc[nt][2], sc[nt][3]));
        }
        mloc0 = fmaxf(mloc0, __shfl_xor_sync(0xffffffffu, mloc0, 1));
        mloc0 = fmaxf(mloc0, __shfl_xor_sync(0xffffffffu, mloc0, 2));
        mloc1 = fmaxf(mloc1, __shfl_xor_sync(0xffffffffu, mloc1, 1));
        mloc1 = fmaxf(mloc1, __shfl_xor_sync(0xffffffffu, mloc1, 2));

        const float mn0 = fmaxf(m0r, mloc0);
        const float mn1 = fmaxf(m1r, mloc1);
        const float f0 = __expf(m0r - mn0);
        const float f1 = __expf(m1r - mn1);
        l0 *= f0; l1 *= f1;
#pragma unroll
        for (int nt = 0; nt < 8; ++nt) {
            acc[nt][0] *= f0; acc[nt][1] *= f0;
            acc[nt][2] *= f1; acc[nt][3] *= f1;
        }

        float s0sum = 0.f, s1sum = 0.f;
#pragma unroll
        for (int nt = 0; nt < 8; ++nt) {
            sc[nt][0] = __expf(sc[nt][0] - mn0);
            sc[nt][1] = __expf(sc[nt][1] - mn0);
            sc[nt][2] = __expf(sc[nt][2] - mn1);
            sc[nt][3] = __expf(sc[nt][3] - mn1);
            s0sum += sc[nt][0] + sc[nt][1];
            s1sum += sc[nt][2] + sc[nt][3];
        }
        s0sum += __shfl_xor_sync(0xffffffffu, s0sum, 1);
        s0sum += __shfl_xor_sync(0xffffffffu, s0sum, 2);
        s1sum += __shfl_xor_sync(0xffffffffu, s1sum, 1);
        s1sum += __shfl_xor_sync(0xffffffffu, s1sum, 2);
        l0 += s0sum; l1 += s1sum;
        m0r = mn0; m1r = mn1;

        // ---- P·V: re-layout P (C-frag -> A-frag) via shfl, then mma ----
#pragma unroll
        for (int kt = 0; kt < 8; ++kt) {
            float x0 = __shfl_sync(0xffffffffu, sc[kt][0], srcA);
            float x1 = __shfl_sync(0xffffffffu, sc[kt][1], srcA);
            float y0 = __shfl_sync(0xffffffffu, sc[kt][0], srcB);
            float y1 = __shfl_sync(0xffffffffu, sc[kt][1], srcB);
            float z0 = __shfl_sync(0xffffffffu, sc[kt][2], srcA);
            float z1 = __shfl_sync(0xffffffffu, sc[kt][3], srcA);
            float u0 = __shfl_sync(0xffffffffu, sc[kt][2], srcB);
            float u1 = __shfl_sync(0xffffffffu, sc[kt][3], srcB);
            unsigned pa[4];
            pa[0] = f2tf32(odd ? x1 : x0);
            pa[1] = f2tf32(odd ? z1 : z0);
            pa[2] = f2tf32(odd ? y1 : y0);
            pa[3] = f2tf32(odd ? u1 : u0);
#pragma unroll
            for (int nt = 0; nt < 8; ++nt) {
                unsigned b0 = Vs[(8 * kt + c4) * 72 + 8 * nt + g];
                unsigned b1 = Vs[(8 * kt + c4 + 4) * 72 + 8 * nt + g];
                mma_tf32(acc[nt], pa, b0, b1);
            }
        }
        __syncthreads();
    }

    // ---- epilogue ----
    const float il0 = 1.0f / l0;
    const float il1 = 1.0f / l1;
    const int r = i0 + r0;
    float* y0p = g_y + (long)(b * T_ + r) * C_ + h * HD_;
    float* y1p = g_y + (long)(b * T_ + r + 8) * C_ + h * HD_;
#pragma unroll
    for (int nt = 0; nt < 8; ++nt) {
        float2 o0; o0.x = acc[nt][0] * il0; o0.y = acc[nt][1] * il0;
        float2 o1; o1.x = acc[nt][2] * il1; o1.y = acc[nt][3] * il1;
        *(float2*)(y0p + 8 * nt + 2 * c4) = o0;
        *(float2*)(y1p + 8 * nt + 2 * c4) = o1;
    }
}

// ---------------- launch ------------------------------------------------------
extern "C" void kernel_launch(void* const* d_in, const int* in_sizes, int n_in,
                              void* d_out, int out_size)
{
    const float* x       = (const float*)d_in[0];
    const float* qkv_w   = (const float*)d_in[1];
    const float* proj_w  = (const float*)d_in[2];
    const float* proj_b  = (const float*)d_in[3];
    const float* curv    = (const float*)d_in[4];
    float* out = (float*)d_out;

    float *qkv, *y;
    cudaGetSymbolAddress((void**)&qkv, g_qkv);
    cudaGetSymbolAddress((void**)&y,   g_y);

    // 1) qkv = x @ qkv_w.T   [4096, 3072]
    gemm_tf32<false><<<dim3((3 * C_) / 64, (B_ * T_) / 128), 256>>>(
        x, qkv_w, nullptr, qkv, B_ * T_, 3 * C_, C_);

    // 2) rope + head layout + scale folding + hyperbolic tq/tk
    rope_kernel<<<B_ * T_, 512>>>(curv);

    // 3) multi-geometry causal attention (tf32 tensor cores) -> g_y [B,T,C]
    attn_mma<<<dim3(T_ / 64, H_, B_), 128>>>(curv);

    // 4) out = y @ proj_w.T + proj_b
    gemm_tf32<true><<<dim3(C_ / 64, (B_ * T_) / 128), 256>>>(
        y, proj_w, proj_b, out, B_ * T_, C_, C_);
}